// round 13
// baseline (speedup 1.0000x reference)
#include <cuda_runtime.h>
#include <math.h>
#include <stdint.h>

// ---------------------------------------------------------------------------
// SelectiveModel: B=32768, T=23, H=64, SLOTS=8, VOCAB=64.
//
// Structural collapse: gating MLP -> S[64][64] sigmoid table (recurrence is
// pure integer state); readout L1 -> QP/MP tables; only the 64x64 L2 GEMM
// remains as real FP work.
//
// R13: gemm moved to TENSOR CORES (3xTF32 mma.sync, error ~1e-6):
//   C^T[v][b] = W^T[v][k] @ H[k][b]  -- H tile is g_HT's native k-major
//   layout (no transpose staging). p0/p1/rh identical to R12.
// ---------------------------------------------------------------------------

#define BTOT 32768

__device__ float g_S  [64 * 64];
__device__ float g_QP [66 * 68];
__device__ float g_MP [64 * 68];
__device__ float g_ED [64 * 32];     // edot[c][j]
__device__ float g_MDT[32 * 64];     // mdot transposed [j][m]
__device__ float g_HT [64 * BTOT];   // k-major h

// ---------------- packed fp32x2 helpers -------------------------------------
__device__ __forceinline__ unsigned long long pk2(float lo, float hi) {
    unsigned long long r;
    asm("mov.b64 %0, {%1, %2};" : "=l"(r) : "f"(lo), "f"(hi));
    return r;
}
__device__ __forceinline__ void upk2(unsigned long long v, float& lo, float& hi) {
    asm("mov.b64 {%0, %1}, %2;" : "=f"(lo), "=f"(hi) : "l"(v));
}
__device__ __forceinline__ void fma2(unsigned long long& d,
                                     unsigned long long a, unsigned long long b) {
    asm("fma.rn.f32x2 %0, %1, %2, %0;" : "+l"(d) : "l"(a), "l"(b));
}

// ---------------- tf32 helpers ----------------------------------------------
__device__ __forceinline__ float tf32r(float x) {
    uint32_t r;
    asm("cvt.rna.tf32.f32 %0, %1;" : "=r"(r) : "f"(x));
    return __uint_as_float(r);
}
__device__ __forceinline__ void mma_tf32(float* c,
    uint32_t a0, uint32_t a1, uint32_t a2, uint32_t a3,
    uint32_t b0, uint32_t b1)
{
    asm volatile(
        "mma.sync.aligned.m16n8k8.row.col.f32.tf32.tf32.f32 "
        "{%0,%1,%2,%3},{%4,%5,%6,%7},{%8,%9},{%0,%1,%2,%3};"
        : "+f"(c[0]), "+f"(c[1]), "+f"(c[2]), "+f"(c[3])
        : "r"(a0), "r"(a1), "r"(a2), "r"(a3), "r"(b0), "r"(b1));
}

// ===================== P0: all independent dot products =====================
__global__ void p0_kernel(
    const float* __restrict__ embed, const float* __restrict__ gw1,
    const float* __restrict__ rw1,   const float* __restrict__ rb1)
{
    const int idx = blockIdx.x * 256 + threadIdx.x;
    if (idx < 4096) {
        const int r = idx >> 5, j = idx & 31;
        const float* e = embed + (r & 63) * 64;
        const float* w = gw1 + ((r >> 6) * 64) * 32 + j;
        float acc[4] = {0.f, 0.f, 0.f, 0.f};
        #pragma unroll
        for (int k0 = 0; k0 < 64; k0 += 8) {
            float wr[8], er[8];
            #pragma unroll
            for (int i = 0; i < 8; i++) { wr[i] = w[(k0 + i) * 32]; er[i] = e[k0 + i]; }
            #pragma unroll
            for (int i = 0; i < 8; i++) acc[i & 3] += er[i] * wr[i];
        }
        const float v = (acc[0] + acc[1]) + (acc[2] + acc[3]);
        if (r < 64) g_ED[r * 32 + j] = v;
        else        g_MDT[j * 64 + (r - 64)] = v;
    } else if (idx < 8320) {
        const int e2 = idx - 4096;
        const int r = e2 >> 6, j = e2 & 63;
        const float* e = embed + r * 64;
        const float* w = rw1 + j;
        float acc[4] = {rb1[j], 0.f, 0.f, 0.f};
        #pragma unroll
        for (int k0 = 0; k0 < 64; k0 += 8) {
            float wr[8], er[8];
            #pragma unroll
            for (int i = 0; i < 8; i++) { wr[i] = w[(k0 + i) * 64]; er[i] = e[k0 + i]; }
            #pragma unroll
            for (int i = 0; i < 8; i++) acc[i & 3] += er[i] * wr[i];
        }
        g_QP[r * 68 + j] = (acc[0] + acc[1]) + (acc[2] + acc[3]);
        if (j < 4) g_QP[r * 68 + 64 + j] = 0.f;
    } else if (idx < 12416) {
        const int e2 = idx - 8320;
        const int r = e2 >> 6, j = e2 & 63;
        const float* e = embed + r * 64;
        const float* w = rw1 + 64 * 64 + j;
        float acc[4] = {0.f, 0.f, 0.f, 0.f};
        #pragma unroll
        for (int k0 = 0; k0 < 64; k0 += 8) {
            float wr[8], er[8];
            #pragma unroll
            for (int i = 0; i < 8; i++) { wr[i] = w[(k0 + i) * 64]; er[i] = e[k0 + i]; }
            #pragma unroll
            for (int i = 0; i < 8; i++) acc[i & 3] += er[i] * wr[i];
        }
        g_MP[r * 68 + j] = (acc[0] + acc[1]) + (acc[2] + acc[3]);
        if (j < 4) g_MP[r * 68 + 64 + j] = 0.f;
    }
}

// ===================== P1: S table combine + sigmoid ========================
__global__ void p1_kernel(
    const float* __restrict__ gb1, const float* __restrict__ gw2,
    const float* __restrict__ gb2)
{
    const int idx = blockIdx.x * 128 + threadIdx.x;
    const int c = idx >> 6, m = idx & 63;
    const float* ed = g_ED + c * 32;
    float acc = gb2[0];
    #pragma unroll
    for (int j0 = 0; j0 < 32; j0 += 8) {
        float md[8], edv[8], gb[8], gw[8];
        #pragma unroll
        for (int i = 0; i < 8; i++) {
            md[i]  = g_MDT[(j0 + i) * 64 + m];
            edv[i] = ed[j0 + i];
            gb[i]  = gb1[j0 + i];
            gw[i]  = gw2[j0 + i];
        }
        #pragma unroll
        for (int i = 0; i < 8; i++)
            acc += fmaxf(edv[i] + md[i] + gb[i], 0.f) * gw[i];
    }
    g_S[c * 64 + m] = 1.f / (1.f + expf(-acc));
}

// ====================== rh: fused recurrence + h gather =====================
// grid 256 x 512; block = 128 batches. Unchanged from R12.
#define RH_SMEM_BYTES ((64 * 65 + 66 * 68 + 64 * 68) * 4 + 128 * 24)

__global__ void __launch_bounds__(512, 2) rh_kernel(
    const int* __restrict__ seqs32, const int* __restrict__ qtok32)
{
    extern __shared__ float sm[];
    float* sS  = sm;                       // [64][65]
    float* sQP = sS + 64 * 65;             // [66][68]
    float* sMP = sQP + 66 * 68;            // [64][68]
    unsigned char* sTok = (unsigned char*)(sMP + 64 * 68);
    const int tid = threadIdx.x, bid = blockIdx.x;

    // int64 vs int32 token dtype detection (odd LE words of small int64 == 0)
    const int oddOr = seqs32[1] | seqs32[3] | seqs32[5] | seqs32[7] |
                      seqs32[9] | seqs32[11] | seqs32[13] | seqs32[15];
    const bool is64 = (oddOr == 0);

    for (int i = tid; i < 4096; i += 512)
        sS[(i >> 6) * 65 + (i & 63)] = g_S[i];
    {
        const float4* g = (const float4*)g_QP; float4* s = (float4*)sQP;
        for (int i = tid; i < 1122; i += 512) s[i] = g[i];
        g = (const float4*)g_MP; s = (float4*)sMP;
        for (int i = tid; i < 1088; i += 512) s[i] = g[i];
    }
    {
        const int base = bid * 128 * 24;
        for (int i = tid; i < 128 * 24; i += 512) {
            const int v = is64 ? seqs32[2 * (base + i)] : seqs32[base + i];
            sTok[i] = (unsigned char)v;
        }
    }
    const int jq = tid & 3;                // j-quarter: adjacent lanes differ
    const int bl = tid >> 2;               // local batch 0..127
    const int b  = bid * 128 + bl;
    const int qt = is64 ? qtok32[2 * b] : qtok32[b];
    __syncthreads();

    // ---- recurrence (integer-key argmax; validated R4-R12) ----
    int moff[8];
    {
        const unsigned char* myTok = sTok + bl * 24;
        int mt[8];
        #pragma unroll
        for (int s = 0; s < 8; s++) mt[s] = myTok[s];
        #pragma unroll
        for (int t = 8; t < 23; t++) {
            const int c = myTok[t];
            const float* Srow = sS + c * 65;
            unsigned key[8];
            #pragma unroll
            for (int s = 0; s < 8; s++) {
                const unsigned bits = __float_as_uint(Srow[mt[s]]);
                key[s] = (bits << 2) | (unsigned)(3 - (s & 3));
            }
            const unsigned a0 = max(max(key[0], key[1]), max(key[2], key[3]));
            const unsigned a1 = max(max(key[4], key[5]), max(key[6], key[7]));
            const int bi = ((a1 >> 2) > (a0 >> 2)) ? (4 + 3 - (int)(a1 & 3))
                                                   : (3 - (int)(a0 & 3));
            #pragma unroll
            for (int s = 0; s < 8; s++) if (bi == s) mt[s] = c;
        }
        #pragma unroll
        for (int s = 0; s < 8; s++) moff[s] = mt[s] * 68 + jq * 16;
    }

    // ---- h gather: this thread's 16 j's ----
    unsigned long long h[8];
    {
        const float* qp = sQP + qt * 68 + jq * 16;
        #pragma unroll
        for (int i = 0; i < 4; i++) {
            const ulonglong2 q = *(const ulonglong2*)(qp + 4 * i);
            h[2 * i] = q.x; h[2 * i + 1] = q.y;
        }
    }
    const unsigned long long E2 = pk2(0.125f, 0.125f);
    #pragma unroll
    for (int s = 0; s < 8; s++) {
        const float* mp = sMP + moff[s];
        #pragma unroll
        for (int i = 0; i < 4; i++) {
            const ulonglong2 m = *(const ulonglong2*)(mp + 4 * i);
            fma2(h[2 * i],     m.x, E2);
            fma2(h[2 * i + 1], m.y, E2);
        }
    }
    // relu + k-major store; each (row, 8-consecutive-batch) = full 32B sector
    float* ht = g_HT + (jq * 16) * BTOT + b;
    #pragma unroll
    for (int i = 0; i < 8; i++) {
        float lo, hi; upk2(h[i], lo, hi);
        ht[(2 * i)     * BTOT] = fmaxf(lo, 0.f);
        ht[(2 * i + 1) * BTOT] = fmaxf(hi, 0.f);
    }
}

// ================= gemm: C^T = W^T @ H via 3xTF32 mma.sync ==================
// grid 256 x 512; block = 128 batches x 64 vocab.
// A = W^T[v][k] (row-major, stride 68 == 4 mod 32: A-frag conflict-free)
// B = H[k][b]   (col-major-by-construction, stride 136 == 8 mod 32: B-frag
//               conflict-free). C[v][b] written directly to out[b][v].
// Warp w (16 warps): v-tile = (w&3)*16, batches (w>>2)*32 .. +31 (4 b-tiles).
#define GEMM_SMEM_FLOATS (2 * 64 * 136 + 2 * 64 * 68 + 64)
#define GEMM_SMEM_BYTES  (GEMM_SMEM_FLOATS * 4)

__global__ void __launch_bounds__(512, 2) gemm_kernel(
    const float* __restrict__ rw2, const float* __restrict__ rb2,
    float* __restrict__ out)
{
    extern __shared__ float sm[];
    float* sHhi = sm;                    // [64 k][136 b]
    float* sHlo = sHhi + 64 * 136;
    float* sWhi = sHlo + 64 * 136;       // [64 v][68 k]
    float* sWlo = sWhi + 64 * 68;
    float* sRB  = sWlo + 64 * 68;        // [64]
    const int tid = threadIdx.x, bid = blockIdx.x;
    const int b0 = bid * 128;

    // ---- stage H (hi/lo tf32 split), native k-major, no transpose ----
    for (int i = tid; i < 2048; i += 512) {
        const int r = i >> 5, c4 = (i & 31) * 4;
        const float4 v = *(const float4*)(g_HT + r * BTOT + b0 + c4);
        float4 h, l;
        h.x = tf32r(v.x); l.x = tf32r(v.x - h.x);
        h.y = tf32r(v.y); l.y = tf32r(v.y - h.y);
        h.z = tf32r(v.z); l.z = tf32r(v.z - h.z);
        h.w = tf32r(v.w); l.w = tf32r(v.w - h.w);
        *(float4*)(sHhi + r * 136 + c4) = h;
        *(float4*)(sHlo + r * 136 + c4) = l;
    }
    // ---- stage W^T (hi/lo), transposed from rw2[k][v] ----
    for (int i = tid; i < 1024; i += 512) {
        const int k = i >> 4, v4 = (i & 15) * 4;
        const float4 wv = *(const float4*)(rw2 + k * 64 + v4);
        const float wa[4] = {wv.x, wv.y, wv.z, wv.w};
        #pragma unroll
        for (int ii = 0; ii < 4; ii++) {
            const float hi = tf32r(wa[ii]);
            sWhi[(v4 + ii) * 68 + k] = hi;
            sWlo[(v4 + ii) * 68 + k] = tf32r(wa[ii] - hi);
        }
    }
    if (tid < 64) sRB[tid] = rb2[tid];
    __syncthreads();

    const int w = tid >> 5, lane = tid & 31;
    const int g = lane >> 2, tg = lane & 3;
    const int v0 = (w & 3) * 16;
    const int bb = (w >> 2) * 32;

    float acc[4][4];
    {
        const float bias0 = sRB[v0 + g], bias1 = sRB[v0 + g + 8];
        #pragma unroll
        for (int t = 0; t < 4; t++) {
            acc[t][0] = bias0; acc[t][1] = bias0;
            acc[t][2] = bias1; acc[t][3] = bias1;
        }
    }

    #pragma unroll
    for (int k0 = 0; k0 < 64; k0 += 8) {
        // A fragments (v0..v0+15, k0..k0+7): hi and lo
        const float* wh = sWhi + (v0 + g) * 68 + k0 + tg;
        const float* wl = sWlo + (v0 + g) * 68 + k0 + tg;
        const uint32_t ah0 = __float_as_uint(wh[0]);
        const uint32_t ah1 = __float_as_uint(wh[8 * 68]);
        const uint32_t ah2 = __float_as_uint(wh[4]);
        const uint32_t ah3 = __float_as_uint(wh[8 * 68 + 4]);
        const uint32_t al0 = __float_as_uint(wl[0]);
        const uint32_t al1 = __float_as_uint(wl[8 * 68]);
        const uint32_t al2 = __float_as_uint(wl[4]);
        const uint32_t al3 = __float_as_uint(wl[8 * 68 + 4]);
        #pragma unroll
        for (int t = 0; t < 4; t++) {
            const int bcol = bb + t * 8 + g;
            const float* hh = sHhi + (k0 + tg) * 136 + bcol;
            const float* hl = sHlo + (k0 + tg) * 136 + bcol;
            const uint32_t bh0 = __float_as_uint(hh[0]);
            const uint32_t bh1 = __float_as_uint(hh[4 * 136]);
            const uint32_t bl0 = __float_as_uint(hl[0]);
            const uint32_t bl1 = __float_as_uint(hl[4 * 136]);
            mma_tf32(acc[t], ah0, ah1, ah2, ah3, bh0, bh1);   // hi*hi
            mma_tf32(acc[t], ah0, ah1, ah2, ah3, bl0, bl1);   // hi*lo
            mma_tf32(acc[t], al0, al1, al2, al3, bh0, bh1);   // lo*hi
        }
    }

    // ---- stores: C[v][b] -> out[b][v]; each STG.32 covers 4x32B sectors ----
    #pragma unroll
    for (int t = 0; t < 4; t++) {
        const int b = b0 + bb + t * 8 + tg * 2;
        const int v = v0 + g;
        out[b * 64 + v]             = acc[t][0];
        out[(b + 1) * 64 + v]       = acc[t][1];
        out[b * 64 + v + 8]         = acc[t][2];
        out[(b + 1) * 64 + v + 8]   = acc[t][3];
    }
}

// ============================== launch ======================================
extern "C" void kernel_launch(void* const* d_in, const int* in_sizes, int n_in,
                              void* d_out, int out_size)
{
    const int*   seqs  = (const int*)  d_in[0];
    const int*   qtok  = (const int*)  d_in[1];
    const float* embed = (const float*)d_in[2];
    const float* gw1   = (const float*)d_in[3];
    const float* gb1   = (const float*)d_in[4];
    const float* gw2   = (const float*)d_in[5];
    const float* gb2   = (const float*)d_in[6];
    const float* rw1   = (const float*)d_in[7];
    const float* rb1   = (const float*)d_in[8];
    const float* rw2   = (const float*)d_in[9];
    const float* rb2   = (const float*)d_in[10];

    cudaFuncSetAttribute(rh_kernel,
                         cudaFuncAttributeMaxDynamicSharedMemorySize,
                         RH_SMEM_BYTES);
    cudaFuncSetAttribute(gemm_kernel,
                         cudaFuncAttributeMaxDynamicSharedMemorySize,
                         GEMM_SMEM_BYTES);

    p0_kernel<<<49, 256>>>(embed, gw1, rw1, rb1);
    p1_kernel<<<32, 128>>>(gb1, gw2, gb2);
    rh_kernel<<<256, 512, RH_SMEM_BYTES>>>(seqs, qtok);
    gemm_kernel<<<256, 512, GEMM_SMEM_BYTES>>>(rw2, rb2, (float*)d_out);
}

// round 14
// speedup vs baseline: 1.2379x; 1.2379x over previous
#include <cuda_runtime.h>
#include <math.h>
#include <stdint.h>

// ---------------------------------------------------------------------------
// SelectiveModel: B=32768, T=23, H=64, SLOTS=8, VOCAB=64.
//
// R14: the slot-gather IS a GEMM. CNT[b][v] = 0.125 * (#slots holding v) is
// EXACT in tf32, so:  h = QP[qt] + CNT @ MP   (2-mma tf32, fp32-accurate)
//                    out = relu(h) @ rw2 + rb2 (3-mma tf32, ~1e-6)
// One fused kernel: recurrence (warps 0-3) || weight staging (warps 4-15)
// -> GEMM1 -> QP-add/relu/split -> GEMM2 -> out. No g_HT round-trip.
// p0/p1 unchanged. Fragment mappings copied from R13 (empirically verified).
// ---------------------------------------------------------------------------

#define BTOT 32768

__device__ float g_S  [64 * 64];
__device__ float g_QP [66 * 68];
__device__ float g_MP [64 * 68];
__device__ float g_ED [64 * 32];
__device__ float g_MDT[32 * 64];

// ---------------- tf32 / mma helpers ----------------------------------------
__device__ __forceinline__ float tf32r(float x) {
    uint32_t r;
    asm("cvt.rna.tf32.f32 %0, %1;" : "=r"(r) : "f"(x));
    return __uint_as_float(r);
}
__device__ __forceinline__ void mma_tf32(float* c,
    uint32_t a0, uint32_t a1, uint32_t a2, uint32_t a3,
    uint32_t b0, uint32_t b1)
{
    asm volatile(
        "mma.sync.aligned.m16n8k8.row.col.f32.tf32.tf32.f32 "
        "{%0,%1,%2,%3},{%4,%5,%6,%7},{%8,%9},{%0,%1,%2,%3};"
        : "+f"(c[0]), "+f"(c[1]), "+f"(c[2]), "+f"(c[3])
        : "r"(a0), "r"(a1), "r"(a2), "r"(a3), "r"(b0), "r"(b1));
}

// ===================== P0: all independent dot products =====================
__global__ void p0_kernel(
    const float* __restrict__ embed, const float* __restrict__ gw1,
    const float* __restrict__ rw1,   const float* __restrict__ rb1)
{
    const int idx = blockIdx.x * 256 + threadIdx.x;
    if (idx < 4096) {
        const int r = idx >> 5, j = idx & 31;
        const float* e = embed + (r & 63) * 64;
        const float* w = gw1 + ((r >> 6) * 64) * 32 + j;
        float acc[4] = {0.f, 0.f, 0.f, 0.f};
        #pragma unroll
        for (int k0 = 0; k0 < 64; k0 += 8) {
            float wr[8], er[8];
            #pragma unroll
            for (int i = 0; i < 8; i++) { wr[i] = w[(k0 + i) * 32]; er[i] = e[k0 + i]; }
            #pragma unroll
            for (int i = 0; i < 8; i++) acc[i & 3] += er[i] * wr[i];
        }
        const float v = (acc[0] + acc[1]) + (acc[2] + acc[3]);
        if (r < 64) g_ED[r * 32 + j] = v;
        else        g_MDT[j * 64 + (r - 64)] = v;
    } else if (idx < 8320) {
        const int e2 = idx - 4096;
        const int r = e2 >> 6, j = e2 & 63;
        const float* e = embed + r * 64;
        const float* w = rw1 + j;
        float acc[4] = {rb1[j], 0.f, 0.f, 0.f};
        #pragma unroll
        for (int k0 = 0; k0 < 64; k0 += 8) {
            float wr[8], er[8];
            #pragma unroll
            for (int i = 0; i < 8; i++) { wr[i] = w[(k0 + i) * 64]; er[i] = e[k0 + i]; }
            #pragma unroll
            for (int i = 0; i < 8; i++) acc[i & 3] += er[i] * wr[i];
        }
        g_QP[r * 68 + j] = (acc[0] + acc[1]) + (acc[2] + acc[3]);
        if (j < 4) g_QP[r * 68 + 64 + j] = 0.f;
    } else if (idx < 12416) {
        const int e2 = idx - 8320;
        const int r = e2 >> 6, j = e2 & 63;
        const float* e = embed + r * 64;
        const float* w = rw1 + 64 * 64 + j;
        float acc[4] = {0.f, 0.f, 0.f, 0.f};
        #pragma unroll
        for (int k0 = 0; k0 < 64; k0 += 8) {
            float wr[8], er[8];
            #pragma unroll
            for (int i = 0; i < 8; i++) { wr[i] = w[(k0 + i) * 64]; er[i] = e[k0 + i]; }
            #pragma unroll
            for (int i = 0; i < 8; i++) acc[i & 3] += er[i] * wr[i];
        }
        g_MP[r * 68 + j] = (acc[0] + acc[1]) + (acc[2] + acc[3]);
        if (j < 4) g_MP[r * 68 + 64 + j] = 0.f;
    }
}

// ===================== P1: S table combine + sigmoid ========================
__global__ void p1_kernel(
    const float* __restrict__ gb1, const float* __restrict__ gw2,
    const float* __restrict__ gb2)
{
    const int idx = blockIdx.x * 128 + threadIdx.x;
    const int c = idx >> 6, m = idx & 63;
    const float* ed = g_ED + c * 32;
    float acc = gb2[0];
    #pragma unroll
    for (int j0 = 0; j0 < 32; j0 += 8) {
        float md[8], edv[8], gb[8], gw[8];
        #pragma unroll
        for (int i = 0; i < 8; i++) {
            md[i]  = g_MDT[(j0 + i) * 64 + m];
            edv[i] = ed[j0 + i];
            gb[i]  = gb1[j0 + i];
            gw[i]  = gw2[j0 + i];
        }
        #pragma unroll
        for (int i = 0; i < 8; i++)
            acc += fmaxf(edv[i] + md[i] + gb[i], 0.f) * gw[i];
    }
    g_S[c * 64 + m] = 1.f / (1.f + expf(-acc));
}

// ================= main: recurrence + CNT-GEMM + out-GEMM ===================
// grid 256 x 512; block = 128 batches; 2 blocks/SM (single wave).
// smem (floats):
//   U [0,17408): phase A: sS[64*65] | sQP[66*68] | sCNT[128*68] (at +8648)
//                phase B: sHhi[64*136] | sHlo[64*136]
//   sMP [64*72] | sW^T [64*68] | sRB[64] | sQT[128 int] | sTok[3072 B]
#define U_F        17408
#define MAIN_SMEM_BYTES ((U_F + 64*72 + 64*68 + 64 + 128) * 4 + 128 * 24)

__global__ void __launch_bounds__(512, 2) main_kernel(
    const int* __restrict__ seqs32, const int* __restrict__ qtok32,
    const float* __restrict__ rw2,  const float* __restrict__ rb2,
    float* __restrict__ out)
{
    extern __shared__ float sm[];
    float* sS   = sm;                      // [64][65]   (phase A)
    float* sQP  = sm + 4160;               // [66][68]   (phase A)
    float* sCNT = sm + 8648;               // [128][68]  (phase A) ends 17352
    float* sHhi = sm;                      // [64][136]  (phase B)
    float* sHlo = sm + 8704;               // [64][136]  (phase B)
    float* sMP  = sm + U_F;                // [64][72]
    float* sW   = sMP + 64 * 72;           // [64][68]  W^T[v][j]
    float* sRB  = sW + 64 * 68;            // [64]
    int*   sQT  = (int*)(sRB + 64);        // [128]
    unsigned char* sTok = (unsigned char*)(sQT + 128);   // 128*24 B
    const int tid = threadIdx.x, bid = blockIdx.x;
    const int w = tid >> 5, lane = tid & 31;
    const int g = lane >> 2, tg = lane & 3;

    // dtype detection (int64 LE of small values -> odd words zero)
    const int oddS = seqs32[1] | seqs32[3] | seqs32[5] | seqs32[7] |
                     seqs32[9] | seqs32[11] | seqs32[13] | seqs32[15];
    const bool is64s = (oddS == 0);
    const int oddQ = qtok32[1] | qtok32[3] | qtok32[5] | qtok32[7] |
                     qtok32[9] | qtok32[11] | qtok32[13] | qtok32[15];
    const bool is64q = (oddQ == 0);

    // ---- phase 0: stage S, QP, tokens, qtok; zero CNT ----
    for (int i = tid; i < 4096; i += 512)
        sS[(i >> 6) * 65 + (i & 63)] = g_S[i];
    for (int i = tid; i < 1122; i += 512)
        ((float4*)sQP)[i] = ((const float4*)g_QP)[i];
    for (int i = tid; i < 128 * 68; i += 512) sCNT[i] = 0.f;
    {
        const int base = bid * 128 * 24;
        for (int i = tid; i < 3072; i += 512) {
            const int v = is64s ? seqs32[2 * (base + i)] : seqs32[base + i];
            sTok[i] = (unsigned char)v;
        }
    }
    if (tid < 128) {
        const int b = bid * 128 + tid;
        sQT[tid] = is64q ? qtok32[2 * b] : qtok32[b];
    }
    __syncthreads();

    // ---- phase 1: warps 0-3 recurrence+scatter; warps 4-15 stage weights ----
    if (w < 4) {
        const unsigned char* myTok = sTok + tid * 24;
        int mt[8];
        #pragma unroll
        for (int s = 0; s < 8; s++) mt[s] = myTok[s];
        #pragma unroll
        for (int t = 8; t < 23; t++) {
            const int c = myTok[t];
            const float* Srow = sS + c * 65;
            unsigned key[8];
            #pragma unroll
            for (int s = 0; s < 8; s++) {
                const unsigned bits = __float_as_uint(Srow[mt[s]]);
                key[s] = (bits << 2) | (unsigned)(3 - (s & 3));
            }
            const unsigned a0 = max(max(key[0], key[1]), max(key[2], key[3]));
            const unsigned a1 = max(max(key[4], key[5]), max(key[6], key[7]));
            const int bi = ((a1 >> 2) > (a0 >> 2)) ? (4 + 3 - (int)(a1 & 3))
                                                   : (3 - (int)(a0 & 3));
            #pragma unroll
            for (int s = 0; s < 8; s++) if (bi == s) mt[s] = c;
        }
        float* cr = sCNT + tid * 68;
        #pragma unroll
        for (int s = 0; s < 8; s++) cr[mt[s]] += 0.125f;   // same-thread RMW
    } else {
        const int t2 = tid - 128;
        for (int i = t2; i < 1024; i += 384) {             // MP -> stride 72
            const int r = i >> 4, c4 = i & 15;
            ((float4*)(sMP + r * 72))[c4] = ((const float4*)g_MP)[r * 17 + c4];
        }
        for (int i = t2; i < 1024; i += 384) {             // W^T transpose
            const int k = i >> 4, v4 = (i & 15) * 4;
            const float4 wv = ((const float4*)rw2)[i];
            sW[(v4 + 0) * 68 + k] = wv.x;
            sW[(v4 + 1) * 68 + k] = wv.y;
            sW[(v4 + 2) * 68 + k] = wv.z;
            sW[(v4 + 3) * 68 + k] = wv.w;
        }
        for (int i = t2; i < 64; i += 384) sRB[i] = rb2[i];
    }
    __syncthreads();

    // ---- phase 2: GEMM1  C1[b][j] = CNT @ MP  (A exact -> 2 mma) ----
    // warp: bm0 = (w&7)*16 (m-tiles of batches), jh = (w>>3)*32 (j half)
    const int bm0 = (w & 7) * 16;
    const int jh  = (w >> 3) * 32;
    float c1[4][4];
    #pragma unroll
    for (int t = 0; t < 4; t++)
        { c1[t][0] = 0.f; c1[t][1] = 0.f; c1[t][2] = 0.f; c1[t][3] = 0.f; }

    #pragma unroll
    for (int k0 = 0; k0 < 64; k0 += 8) {
        const float* ap = sCNT + (bm0 + g) * 68 + k0 + tg;
        const uint32_t a0 = __float_as_uint(ap[0]);
        const uint32_t a1 = __float_as_uint(ap[8 * 68]);
        const uint32_t a2 = __float_as_uint(ap[4]);
        const uint32_t a3 = __float_as_uint(ap[8 * 68 + 4]);   // exact tf32
        #pragma unroll
        for (int t = 0; t < 4; t++) {
            const int jn0 = jh + t * 8;
            const float b0f = sMP[(k0 + tg) * 72 + jn0 + g];
            const float b1f = sMP[(k0 + tg + 4) * 72 + jn0 + g];
            const float b0h = tf32r(b0f), b1h = tf32r(b1f);
            const uint32_t b0l = __float_as_uint(tf32r(b0f - b0h));
            const uint32_t b1l = __float_as_uint(tf32r(b1f - b1h));
            mma_tf32(c1[t], a0, a1, a2, a3,
                     __float_as_uint(b0h), __float_as_uint(b1h));
            mma_tf32(c1[t], a0, a1, a2, a3, b0l, b1l);
        }
    }

    // ---- QP add + relu + tf32 split (in regs) ----
    float hhi[16], hlo[16];
    {
        const int qt0 = sQT[bm0 + g], qt1 = sQT[bm0 + 8 + g];
        #pragma unroll
        for (int t = 0; t < 4; t++) {
            const int jj = jh + t * 8 + 2 * tg;
            const float2 q0 = *(const float2*)(sQP + qt0 * 68 + jj);
            const float2 q1 = *(const float2*)(sQP + qt1 * 68 + jj);
            const float v0 = fmaxf(c1[t][0] + q0.x, 0.f);
            const float v1 = fmaxf(c1[t][1] + q0.y, 0.f);
            const float v2 = fmaxf(c1[t][2] + q1.x, 0.f);
            const float v3 = fmaxf(c1[t][3] + q1.y, 0.f);
            hhi[t*4+0] = tf32r(v0); hlo[t*4+0] = tf32r(v0 - hhi[t*4+0]);
            hhi[t*4+1] = tf32r(v1); hlo[t*4+1] = tf32r(v1 - hhi[t*4+1]);
            hhi[t*4+2] = tf32r(v2); hlo[t*4+2] = tf32r(v2 - hhi[t*4+2]);
            hhi[t*4+3] = tf32r(v3); hlo[t*4+3] = tf32r(v3 - hhi[t*4+3]);
        }
    }
    __syncthreads();          // all reads of sS/sQP/sCNT done

    // ---- phase 3: store H (j-major) into U region ----
    #pragma unroll
    for (int t = 0; t < 4; t++) {
        const int jj = jh + t * 8 + 2 * tg;
        sHhi[jj * 136 + bm0 + g]           = hhi[t*4+0];
        sHhi[(jj + 1) * 136 + bm0 + g]     = hhi[t*4+1];
        sHhi[jj * 136 + bm0 + 8 + g]       = hhi[t*4+2];
        sHhi[(jj + 1) * 136 + bm0 + 8 + g] = hhi[t*4+3];
        sHlo[jj * 136 + bm0 + g]           = hlo[t*4+0];
        sHlo[(jj + 1) * 136 + bm0 + g]     = hlo[t*4+1];
        sHlo[jj * 136 + bm0 + 8 + g]       = hlo[t*4+2];
        sHlo[(jj + 1) * 136 + bm0 + 8 + g] = hlo[t*4+3];
    }
    __syncthreads();

    // ---- phase 4: GEMM2  out^T[v][b] = W^T @ H  (3 mma, R13-verified) ----
    const int v0 = (w & 3) * 16;
    const int bb = (w >> 2) * 32;
    float acc[4][4];
    {
        const float bias0 = sRB[v0 + g], bias1 = sRB[v0 + g + 8];
        #pragma unroll
        for (int t = 0; t < 4; t++) {
            acc[t][0] = bias0; acc[t][1] = bias0;
            acc[t][2] = bias1; acc[t][3] = bias1;
        }
    }
    #pragma unroll
    for (int k0 = 0; k0 < 64; k0 += 8) {
        const float* wp = sW + (v0 + g) * 68 + k0 + tg;
        const float a0f = wp[0], a1f = wp[8 * 68];
        const float a2f = wp[4], a3f = wp[8 * 68 + 4];
        const float a0h = tf32r(a0f), a1h = tf32r(a1f);
        const float a2h = tf32r(a2f), a3h = tf32r(a3f);
        const uint32_t ah0 = __float_as_uint(a0h), ah1 = __float_as_uint(a1h);
        const uint32_t ah2 = __float_as_uint(a2h), ah3 = __float_as_uint(a3h);
        const uint32_t al0 = __float_as_uint(tf32r(a0f - a0h));
        const uint32_t al1 = __float_as_uint(tf32r(a1f - a1h));
        const uint32_t al2 = __float_as_uint(tf32r(a2f - a2h));
        const uint32_t al3 = __float_as_uint(tf32r(a3f - a3h));
        #pragma unroll
        for (int t = 0; t < 4; t++) {
            const int bcol = bb + t * 8 + g;
            const uint32_t bh0 = __float_as_uint(sHhi[(k0 + tg) * 136 + bcol]);
            const uint32_t bh1 = __float_as_uint(sHhi[(k0 + tg + 4) * 136 + bcol]);
            const uint32_t bl0 = __float_as_uint(sHlo[(k0 + tg) * 136 + bcol]);
            const uint32_t bl1 = __float_as_uint(sHlo[(k0 + tg + 4) * 136 + bcol]);
            mma_tf32(acc[t], ah0, ah1, ah2, ah3, bh0, bh1);   // hi*hi
            mma_tf32(acc[t], ah0, ah1, ah2, ah3, bl0, bl1);   // hi*lo
            mma_tf32(acc[t], al0, al1, al2, al3, bh0, bh1);   // lo*hi
        }
    }
    #pragma unroll
    for (int t = 0; t < 4; t++) {
        const int b = bid * 128 + bb + t * 8 + tg * 2;
        const int v = v0 + g;
        out[b * 64 + v]           = acc[t][0];
        out[(b + 1) * 64 + v]     = acc[t][1];
        out[b * 64 + v + 8]       = acc[t][2];
        out[(b + 1) * 64 + v + 8] = acc[t][3];
    }
}

// ============================== launch ======================================
extern "C" void kernel_launch(void* const* d_in, const int* in_sizes, int n_in,
                              void* d_out, int out_size)
{
    const int*   seqs  = (const int*)  d_in[0];
    const int*   qtok  = (const int*)  d_in[1];
    const float* embed = (const float*)d_in[2];
    const float* gw1   = (const float*)d_in[3];
    const float* gb1   = (const float*)d_in[4];
    const float* gw2   = (const float*)d_in[5];
    const float* gb2   = (const float*)d_in[6];
    const float* rw1   = (const float*)d_in[7];
    const float* rb1   = (const float*)d_in[8];
    const float* rw2   = (const float*)d_in[9];
    const float* rb2   = (const float*)d_in[10];

    cudaFuncSetAttribute(main_kernel,
                         cudaFuncAttributeMaxDynamicSharedMemorySize,
                         MAIN_SMEM_BYTES);

    p0_kernel<<<49, 256>>>(embed, gw1, rw1, rb1);
    p1_kernel<<<32, 128>>>(gb1, gw2, gb2);
    main_kernel<<<256, 512, MAIN_SMEM_BYTES>>>(seqs, qtok, rw2, rb2,
                                               (float*)d_out);
}

// round 15
// speedup vs baseline: 1.2500x; 1.0098x over previous
#include <cuda_runtime.h>
#include <math.h>
#include <stdint.h>

// ---------------------------------------------------------------------------
// SelectiveModel: B=32768, T=23, H=64, SLOTS=8, VOCAB=64.
//
// R15:
//   pre : ONE launch. Blocks 0-96: all 12416 dot-64s, 4 threads/dot (k-split
//         + shfl reduce, single load wave). Blocks 97-128: S-table combine,
//         spin-synced on a self-resetting counter (all 129 blocks co-resident
//         -> deadlock-free; graph-replay safe).
//   main: R14 fused recurrence + CNT-GEMM + out-GEMM (tensor cores), with
//         lo-residual cvts removed (HW tf32 truncation).
// ---------------------------------------------------------------------------

#define BTOT 32768

__device__ float g_S  [64 * 64];
__device__ float g_QP [66 * 68];
__device__ float g_MP [64 * 68];
__device__ float g_ED [64 * 32];
__device__ float g_MDT[32 * 64];
__device__ int   g_sync1 = 0;    // p0-done counter (self-resetting)
__device__ int   g_sync2 = 0;    // p1-done counter (self-resetting)

// ---------------- tf32 / mma helpers ----------------------------------------
__device__ __forceinline__ float tf32r(float x) {
    uint32_t r;
    asm("cvt.rna.tf32.f32 %0, %1;" : "=r"(r) : "f"(x));
    return __uint_as_float(r);
}
__device__ __forceinline__ void mma_tf32(float* c,
    uint32_t a0, uint32_t a1, uint32_t a2, uint32_t a3,
    uint32_t b0, uint32_t b1)
{
    asm volatile(
        "mma.sync.aligned.m16n8k8.row.col.f32.tf32.tf32.f32 "
        "{%0,%1,%2,%3},{%4,%5,%6,%7},{%8,%9},{%0,%1,%2,%3};"
        : "+f"(c[0]), "+f"(c[1]), "+f"(c[2]), "+f"(c[3])
        : "r"(a0), "r"(a1), "r"(a2), "r"(a3), "r"(b0), "r"(b1));
}

// =================== pre: dots (blocks 0-96) + S (97-128) ===================
__global__ void pre_kernel(
    const float* __restrict__ embed, const float* __restrict__ gw1,
    const float* __restrict__ rw1,   const float* __restrict__ rb1,
    const float* __restrict__ gb1,   const float* __restrict__ gw2,
    const float* __restrict__ gb2)
{
    const int tid = threadIdx.x, bid = blockIdx.x;

    if (bid < 97) {
        // ---- p0: 4 threads per dot, k-split 16 each, shfl reduce ----
        const int gid = bid * 512 + tid;
        const int d = gid >> 2, tg = gid & 3;
        const int k0 = tg * 16;
        float total = 0.f;
        if (d < 4096) {
            const int r = d >> 5, j = d & 31;
            const float* e = embed + (r & 63) * 64 + k0;
            const float* w = gw1 + ((r >> 6) * 64 + k0) * 32 + j;
            float er[16], wr[16];
            #pragma unroll
            for (int i = 0; i < 16; i++) { er[i] = e[i]; wr[i] = w[i * 32]; }
            float a[4] = {0.f, 0.f, 0.f, 0.f};
            #pragma unroll
            for (int i = 0; i < 16; i++) a[i & 3] += er[i] * wr[i];
            float p = (a[0] + a[1]) + (a[2] + a[3]);
            p += __shfl_xor_sync(0xffffffff, p, 1, 4);
            p += __shfl_xor_sync(0xffffffff, p, 2, 4);
            if (tg == 0) {
                if (r < 64) g_ED[r * 32 + j] = p;
                else        g_MDT[j * 64 + (r - 64)] = p;
            }
            total = p;   // keep compiler honest
        } else {
            const bool isQP = (d < 8320);
            const int e2 = isQP ? (d - 4096) : (d - 8320);
            const int r = e2 >> 6, j = e2 & 63;
            const float* e = embed + r * 64 + k0;
            const float* w = rw1 + (isQP ? 0 : 64 * 64) + k0 * 64 + j;
            float er[16], wr[16];
            #pragma unroll
            for (int i = 0; i < 16; i++) { er[i] = e[i]; wr[i] = w[i * 64]; }
            float a[4] = {0.f, 0.f, 0.f, 0.f};
            #pragma unroll
            for (int i = 0; i < 16; i++) a[i & 3] += er[i] * wr[i];
            float p = (a[0] + a[1]) + (a[2] + a[3]);
            p += __shfl_xor_sync(0xffffffff, p, 1, 4);
            p += __shfl_xor_sync(0xffffffff, p, 2, 4);
            if (tg == 0) {
                if (isQP) {
                    g_QP[r * 68 + j] = p + rb1[j];
                    if (j < 4) g_QP[r * 68 + 64 + j] = 0.f;
                } else {
                    g_MP[r * 68 + j] = p;
                    if (j < 4) g_MP[r * 68 + 64 + j] = 0.f;
                }
            }
            total = p;
        }
        (void)total;
        __syncthreads();
        if (tid == 0) {
            __threadfence();
            atomicAdd(&g_sync1, 1);
        }
    } else {
        // ---- p1: spin until all 97 p0 blocks done, then S combine ----
        if (tid == 0) {
            while (*(volatile int*)&g_sync1 < 97) { }
            __threadfence();
        }
        __syncthreads();

        const int gid = (bid - 97) * 512 + tid;   // 16384 = 4096 entries x 4
        const int idx = gid >> 2, tg = gid & 3;
        const int c = idx >> 6, m = idx & 63;
        const int j0 = tg * 8;
        const float* ed = g_ED + c * 32 + j0;
        float md[8], edv[8], gb[8], gw[8];
        #pragma unroll
        for (int i = 0; i < 8; i++) {
            md[i]  = g_MDT[(j0 + i) * 64 + m];
            edv[i] = ed[i];
            gb[i]  = gb1[j0 + i];
            gw[i]  = gw2[j0 + i];
        }
        float p = 0.f;
        #pragma unroll
        for (int i = 0; i < 8; i++)
            p += fmaxf(edv[i] + md[i] + gb[i], 0.f) * gw[i];
        p += __shfl_xor_sync(0xffffffff, p, 1, 4);
        p += __shfl_xor_sync(0xffffffff, p, 2, 4);
        if (tg == 0) {
            const float acc = p + gb2[0];
            g_S[c * 64 + m] = 1.f / (1.f + expf(-acc));
        }

        // ---- self-reset for graph replay ----
        __syncthreads();
        if (tid == 0) {
            __threadfence();
            const int old = atomicAdd(&g_sync2, 1);
            if (old == 31) {
                *(volatile int*)&g_sync1 = 0;
                *(volatile int*)&g_sync2 = 0;
                __threadfence();
            }
        }
    }
}

// ================= main: recurrence + CNT-GEMM + out-GEMM ===================
// grid 256 x 512; block = 128 batches; 2 blocks/SM (single wave).
#define U_F        17408
#define MAIN_SMEM_BYTES ((U_F + 64*72 + 64*68 + 64 + 128) * 4 + 128 * 24)

__global__ void __launch_bounds__(512, 2) main_kernel(
    const int* __restrict__ seqs32, const int* __restrict__ qtok32,
    const float* __restrict__ rw2,  const float* __restrict__ rb2,
    float* __restrict__ out)
{
    extern __shared__ float sm[];
    float* sS   = sm;                      // [64][65]   (phase A)
    float* sQP  = sm + 4160;               // [66][68]   (phase A)
    float* sCNT = sm + 8648;               // [128][68]  (phase A)
    float* sHhi = sm;                      // [64][136]  (phase B)
    float* sHlo = sm + 8704;               // [64][136]  (phase B)
    float* sMP  = sm + U_F;                // [64][72]
    float* sW   = sMP + 64 * 72;           // [64][68]  W^T[v][j]
    float* sRB  = sW + 64 * 68;            // [64]
    int*   sQT  = (int*)(sRB + 64);        // [128]
    unsigned char* sTok = (unsigned char*)(sQT + 128);
    const int tid = threadIdx.x, bid = blockIdx.x;
    const int w = tid >> 5, lane = tid & 31;
    const int g = lane >> 2, tg = lane & 3;

    const int oddS = seqs32[1] | seqs32[3] | seqs32[5] | seqs32[7] |
                     seqs32[9] | seqs32[11] | seqs32[13] | seqs32[15];
    const bool is64s = (oddS == 0);
    const int oddQ = qtok32[1] | qtok32[3] | qtok32[5] | qtok32[7] |
                     qtok32[9] | qtok32[11] | qtok32[13] | qtok32[15];
    const bool is64q = (oddQ == 0);

    // ---- phase 0: stage S, QP, tokens, qtok; zero CNT ----
    for (int i = tid; i < 4096; i += 512)
        sS[(i >> 6) * 65 + (i & 63)] = g_S[i];
    for (int i = tid; i < 1122; i += 512)
        ((float4*)sQP)[i] = ((const float4*)g_QP)[i];
    for (int i = tid; i < 128 * 68; i += 512) sCNT[i] = 0.f;
    {
        const int base = bid * 128 * 24;
        for (int i = tid; i < 3072; i += 512) {
            const int v = is64s ? seqs32[2 * (base + i)] : seqs32[base + i];
            sTok[i] = (unsigned char)v;
        }
    }
    if (tid < 128) {
        const int b = bid * 128 + tid;
        sQT[tid] = is64q ? qtok32[2 * b] : qtok32[b];
    }
    __syncthreads();

    // ---- phase 1: warps 0-3 recurrence+scatter; warps 4-15 stage weights ----
    if (w < 4) {
        const unsigned char* myTok = sTok + tid * 24;
        int mt[8];
        #pragma unroll
        for (int s = 0; s < 8; s++) mt[s] = myTok[s];
        #pragma unroll
        for (int t = 8; t < 23; t++) {
            const int c = myTok[t];
            const float* Srow = sS + c * 65;
            unsigned key[8];
            #pragma unroll
            for (int s = 0; s < 8; s++) {
                const unsigned bits = __float_as_uint(Srow[mt[s]]);
                key[s] = (bits << 2) | (unsigned)(3 - (s & 3));
            }
            const unsigned a0 = max(max(key[0], key[1]), max(key[2], key[3]));
            const unsigned a1 = max(max(key[4], key[5]), max(key[6], key[7]));
            const int bi = ((a1 >> 2) > (a0 >> 2)) ? (4 + 3 - (int)(a1 & 3))
                                                   : (3 - (int)(a0 & 3));
            #pragma unroll
            for (int s = 0; s < 8; s++) if (bi == s) mt[s] = c;
        }
        float* cr = sCNT + tid * 68;
        #pragma unroll
        for (int s = 0; s < 8; s++) cr[mt[s]] += 0.125f;
    } else {
        const int t2 = tid - 128;
        for (int i = t2; i < 1024; i += 384) {
            const int r = i >> 4, c4 = i & 15;
            ((float4*)(sMP + r * 72))[c4] = ((const float4*)g_MP)[r * 17 + c4];
        }
        for (int i = t2; i < 1024; i += 384) {
            const int k = i >> 4, v4 = (i & 15) * 4;
            const float4 wv = ((const float4*)rw2)[i];
            sW[(v4 + 0) * 68 + k] = wv.x;
            sW[(v4 + 1) * 68 + k] = wv.y;
            sW[(v4 + 2) * 68 + k] = wv.z;
            sW[(v4 + 3) * 68 + k] = wv.w;
        }
        for (int i = t2; i < 64; i += 384) sRB[i] = rb2[i];
    }
    __syncthreads();

    // ---- phase 2: GEMM1  C1[b][j] = CNT @ MP  (A exact -> 2 mma) ----
    const int bm0 = (w & 7) * 16;
    const int jh  = (w >> 3) * 32;
    float c1[4][4];
    #pragma unroll
    for (int t = 0; t < 4; t++)
        { c1[t][0] = 0.f; c1[t][1] = 0.f; c1[t][2] = 0.f; c1[t][3] = 0.f; }

    #pragma unroll
    for (int k0 = 0; k0 < 64; k0 += 8) {
        const float* ap = sCNT + (bm0 + g) * 68 + k0 + tg;
        const uint32_t a0 = __float_as_uint(ap[0]);
        const uint32_t a1 = __float_as_uint(ap[8 * 68]);
        const uint32_t a2 = __float_as_uint(ap[4]);
        const uint32_t a3 = __float_as_uint(ap[8 * 68 + 4]);
        #pragma unroll
        for (int t = 0; t < 4; t++) {
            const int jn0 = jh + t * 8;
            const float b0f = sMP[(k0 + tg) * 72 + jn0 + g];
            const float b1f = sMP[(k0 + tg + 4) * 72 + jn0 + g];
            const float b0h = tf32r(b0f), b1h = tf32r(b1f);
            const uint32_t b0l = __float_as_uint(b0f - b0h);  // HW-truncated lo
            const uint32_t b1l = __float_as_uint(b1f - b1h);
            mma_tf32(c1[t], a0, a1, a2, a3,
                     __float_as_uint(b0h), __float_as_uint(b1h));
            mma_tf32(c1[t], a0, a1, a2, a3, b0l, b1l);
        }
    }

    // ---- QP add + relu + tf32 split (in regs) ----
    float hhi[16], hlo[16];
    {
        const int qt0 = sQT[bm0 + g], qt1 = sQT[bm0 + 8 + g];
        #pragma unroll
        for (int t = 0; t < 4; t++) {
            const int jj = jh + t * 8 + 2 * tg;
            const float2 q0 = *(const float2*)(sQP + qt0 * 68 + jj);
            const float2 q1 = *(const float2*)(sQP + qt1 * 68 + jj);
            const float v0 = fmaxf(c1[t][0] + q0.x, 0.f);
            const float v1 = fmaxf(c1[t][1] + q0.y, 0.f);
            const float v2 = fmaxf(c1[t][2] + q1.x, 0.f);
            const float v3 = fmaxf(c1[t][3] + q1.y, 0.f);
            hhi[t*4+0] = tf32r(v0); hlo[t*4+0] = v0 - hhi[t*4+0];
            hhi[t*4+1] = tf32r(v1); hlo[t*4+1] = v1 - hhi[t*4+1];
            hhi[t*4+2] = tf32r(v2); hlo[t*4+2] = v2 - hhi[t*4+2];
            hhi[t*4+3] = tf32r(v3); hlo[t*4+3] = v3 - hhi[t*4+3];
        }
    }
    __syncthreads();

    // ---- phase 3: store H (j-major) into U region ----
    #pragma unroll
    for (int t = 0; t < 4; t++) {
        const int jj = jh + t * 8 + 2 * tg;
        sHhi[jj * 136 + bm0 + g]           = hhi[t*4+0];
        sHhi[(jj + 1) * 136 + bm0 + g]     = hhi[t*4+1];
        sHhi[jj * 136 + bm0 + 8 + g]       = hhi[t*4+2];
        sHhi[(jj + 1) * 136 + bm0 + 8 + g] = hhi[t*4+3];
        sHlo[jj * 136 + bm0 + g]           = hlo[t*4+0];
        sHlo[(jj + 1) * 136 + bm0 + g]     = hlo[t*4+1];
        sHlo[jj * 136 + bm0 + 8 + g]       = hlo[t*4+2];
        sHlo[(jj + 1) * 136 + bm0 + 8 + g] = hlo[t*4+3];
    }
    __syncthreads();

    // ---- phase 4: GEMM2  out^T[v][b] = W^T @ H  (3 mma) ----
    const int v0 = (w & 3) * 16;
    const int bb = (w >> 2) * 32;
    float acc[4][4];
    {
        const float bias0 = sRB[v0 + g], bias1 = sRB[v0 + g + 8];
        #pragma unroll
        for (int t = 0; t < 4; t++) {
            acc[t][0] = bias0; acc[t][1] = bias0;
            acc[t][2] = bias1; acc[t][3] = bias1;
        }
    }
    #pragma unroll
    for (int k0 = 0; k0 < 64; k0 += 8) {
        const float* wp = sW + (v0 + g) * 68 + k0 + tg;
        const float a0f = wp[0], a1f = wp[8 * 68];
        const float a2f = wp[4], a3f = wp[8 * 68 + 4];
        const float a0h = tf32r(a0f), a1h = tf32r(a1f);
        const float a2h = tf32r(a2f), a3h = tf32r(a3f);
        const uint32_t ah0 = __float_as_uint(a0h), ah1 = __float_as_uint(a1h);
        const uint32_t ah2 = __float_as_uint(a2h), ah3 = __float_as_uint(a3h);
        const uint32_t al0 = __float_as_uint(a0f - a0h);      // HW-truncated lo
        const uint32_t al1 = __float_as_uint(a1f - a1h);
        const uint32_t al2 = __float_as_uint(a2f - a2h);
        const uint32_t al3 = __float_as_uint(a3f - a3h);
        #pragma unroll
        for (int t = 0; t < 4; t++) {
            const int bcol = bb + t * 8 + g;
            const uint32_t bh0 = __float_as_uint(sHhi[(k0 + tg) * 136 + bcol]);
            const uint32_t bh1 = __float_as_uint(sHhi[(k0 + tg + 4) * 136 + bcol]);
            const uint32_t bl0 = __float_as_uint(sHlo[(k0 + tg) * 136 + bcol]);
            const uint32_t bl1 = __float_as_uint(sHlo[(k0 + tg + 4) * 136 + bcol]);
            mma_tf32(acc[t], ah0, ah1, ah2, ah3, bh0, bh1);
            mma_tf32(acc[t], ah0, ah1, ah2, ah3, bl0, bl1);
            mma_tf32(acc[t], al0, al1, al2, al3, bh0, bh1);
        }
    }
    #pragma unroll
    for (int t = 0; t < 4; t++) {
        const int b = bid * 128 + bb + t * 8 + tg * 2;
        const int v = v0 + g;
        out[b * 64 + v]           = acc[t][0];
        out[(b + 1) * 64 + v]     = acc[t][1];
        out[b * 64 + v + 8]       = acc[t][2];
        out[(b + 1) * 64 + v + 8] = acc[t][3];
    }
}

// ============================== launch ======================================
extern "C" void kernel_launch(void* const* d_in, const int* in_sizes, int n_in,
                              void* d_out, int out_size)
{
    const int*   seqs  = (const int*)  d_in[0];
    const int*   qtok  = (const int*)  d_in[1];
    const float* embed = (const float*)d_in[2];
    const float* gw1   = (const float*)d_in[3];
    const float* gb1   = (const float*)d_in[4];
    const float* gw2   = (const float*)d_in[5];
    const float* gb2   = (const float*)d_in[6];
    const float* rw1   = (const float*)d_in[7];
    const float* rb1   = (const float*)d_in[8];
    const float* rw2   = (const float*)d_in[9];
    const float* rb2   = (const float*)d_in[10];

    cudaFuncSetAttribute(main_kernel,
                         cudaFuncAttributeMaxDynamicSharedMemorySize,
                         MAIN_SMEM_BYTES);

    pre_kernel<<<129, 512>>>(embed, gw1, rw1, rb1, gb1, gw2, gb2);
    main_kernel<<<256, 512, MAIN_SMEM_BYTES>>>(seqs, qtok, rw2, rb2,
                                               (float*)d_out);
}

// round 16
// speedup vs baseline: 1.4004x; 1.1204x over previous
#include <cuda_runtime.h>
#include <math.h>
#include <stdint.h>

// ---------------------------------------------------------------------------
// SelectiveModel: B=32768, T=23, H=64, SLOTS=8, VOCAB=64.
//
// R16: spend the precision budget (tol 1e-3, we were at 5.7e-7):
//   GEMM1 (CNT@MP): CNT exact in tf32, MP pre-rounded in pre  -> 1 mma, 0 ALU
//   GEMM2 (W^T@H) : W hi/lo pre-split+transposed in pre, H single tf32
//                   -> 2 mma, 0 in-loop cvt/sub, sHlo array deleted
//   S table stored as pre-shifted integer keys (g_Sk = bits<<2, padded 68)
//   -> all main staging is float4 copies. smem 109 -> 90 KB/block.
// Expected rel_err ~1-3e-4 (norm metric), well under 1e-3.
// ---------------------------------------------------------------------------

#define BTOT 32768

__device__ uint32_t g_Sk [64 * 68];   // sigmoid-score keys, bits<<2, padded
__device__ float    g_QP [66 * 68];   // exact fp32
__device__ float    g_MP [64 * 68];   // tf32-ROUNDED (GEMM1 B operand)
__device__ float    g_Whi[64 * 68];   // W^T hi (tf32-rounded), [v][k]
__device__ float    g_Wlo[64 * 68];   // W^T lo residual (fp32)
__device__ float    g_ED [64 * 32];
__device__ float    g_MDT[32 * 64];
__device__ int      g_sync1 = 0;
__device__ int      g_sync2 = 0;

// ---------------- tf32 / mma helpers ----------------------------------------
__device__ __forceinline__ float tf32r(float x) {
    uint32_t r;
    asm("cvt.rna.tf32.f32 %0, %1;" : "=r"(r) : "f"(x));
    return __uint_as_float(r);
}
__device__ __forceinline__ void mma_tf32(float* c,
    uint32_t a0, uint32_t a1, uint32_t a2, uint32_t a3,
    uint32_t b0, uint32_t b1)
{
    asm volatile(
        "mma.sync.aligned.m16n8k8.row.col.f32.tf32.tf32.f32 "
        "{%0,%1,%2,%3},{%4,%5,%6,%7},{%8,%9},{%0,%1,%2,%3};"
        : "+f"(c[0]), "+f"(c[1]), "+f"(c[2]), "+f"(c[3])
        : "r"(a0), "r"(a1), "r"(a2), "r"(a3), "r"(b0), "r"(b1));
}

// =================== pre: dots (blocks 0-96) + S/W (97-128) =================
__global__ void pre_kernel(
    const float* __restrict__ embed, const float* __restrict__ gw1,
    const float* __restrict__ rw1,   const float* __restrict__ rb1,
    const float* __restrict__ gb1,   const float* __restrict__ gw2,
    const float* __restrict__ gb2,   const float* __restrict__ rw2)
{
    const int tid = threadIdx.x, bid = blockIdx.x;

    if (bid < 97) {
        // ---- p0: 4 threads per dot, k-split 16 each, shfl reduce ----
        const int gid = bid * 512 + tid;
        const int d = gid >> 2, tg = gid & 3;
        const int k0 = tg * 16;
        if (d < 4096) {
            const int r = d >> 5, j = d & 31;
            const float* e = embed + (r & 63) * 64 + k0;
            const float* w = gw1 + ((r >> 6) * 64 + k0) * 32 + j;
            float er[16], wr[16];
            #pragma unroll
            for (int i = 0; i < 16; i++) { er[i] = e[i]; wr[i] = w[i * 32]; }
            float a[4] = {0.f, 0.f, 0.f, 0.f};
            #pragma unroll
            for (int i = 0; i < 16; i++) a[i & 3] += er[i] * wr[i];
            float p = (a[0] + a[1]) + (a[2] + a[3]);
            p += __shfl_xor_sync(0xffffffff, p, 1, 4);
            p += __shfl_xor_sync(0xffffffff, p, 2, 4);
            if (tg == 0) {
                if (r < 64) g_ED[r * 32 + j] = p;
                else        g_MDT[j * 64 + (r - 64)] = p;
            }
        } else {
            const bool isQP = (d < 8320);
            const int e2 = isQP ? (d - 4096) : (d - 8320);
            const int r = e2 >> 6, j = e2 & 63;
            const float* e = embed + r * 64 + k0;
            const float* w = rw1 + (isQP ? 0 : 64 * 64) + k0 * 64 + j;
            float er[16], wr[16];
            #pragma unroll
            for (int i = 0; i < 16; i++) { er[i] = e[i]; wr[i] = w[i * 64]; }
            float a[4] = {0.f, 0.f, 0.f, 0.f};
            #pragma unroll
            for (int i = 0; i < 16; i++) a[i & 3] += er[i] * wr[i];
            float p = (a[0] + a[1]) + (a[2] + a[3]);
            p += __shfl_xor_sync(0xffffffff, p, 1, 4);
            p += __shfl_xor_sync(0xffffffff, p, 2, 4);
            if (tg == 0) {
                if (isQP) {
                    g_QP[r * 68 + j] = p + rb1[j];
                    if (j < 4) g_QP[r * 68 + 64 + j] = 0.f;
                } else {
                    g_MP[r * 68 + j] = tf32r(p);   // pre-rounded for GEMM1
                    if (j < 4) g_MP[r * 68 + 64 + j] = 0.f;
                }
            }
        }
        __syncthreads();
        if (tid == 0) {
            __threadfence();
            atomicAdd(&g_sync1, 1);
        }
    } else {
        const int gid = (bid - 97) * 512 + tid;   // [0, 16384)

        // ---- W^T split (independent of p0): first 4096 threads ----
        if (gid < 4096) {
            const int k = gid >> 6, v = gid & 63;
            const float wv = rw2[gid];             // coalesced
            const float hi = tf32r(wv);
            g_Whi[v * 68 + k] = hi;
            g_Wlo[v * 68 + k] = wv - hi;
        }

        // ---- p1: spin until all 97 p0 blocks done, then S keys ----
        if (tid == 0) {
            while (*(volatile int*)&g_sync1 < 97) { }
            __threadfence();
        }
        __syncthreads();

        const int idx = gid >> 2, tg = gid & 3;
        const int c = idx >> 6, m = idx & 63;
        const int j0 = tg * 8;
        const float* ed = g_ED + c * 32 + j0;
        float md[8], edv[8], gb[8], gw[8];
        #pragma unroll
        for (int i = 0; i < 8; i++) {
            md[i]  = g_MDT[(j0 + i) * 64 + m];
            edv[i] = ed[i];
            gb[i]  = gb1[j0 + i];
            gw[i]  = gw2[j0 + i];
        }
        float p = 0.f;
        #pragma unroll
        for (int i = 0; i < 8; i++)
            p += fmaxf(edv[i] + md[i] + gb[i], 0.f) * gw[i];
        p += __shfl_xor_sync(0xffffffff, p, 1, 4);
        p += __shfl_xor_sync(0xffffffff, p, 2, 4);
        if (tg == 0) {
            const float s = 1.f / (1.f + expf(-(p + gb2[0])));
            g_Sk[c * 68 + m] = __float_as_uint(s) << 2;   // pre-shifted key
        }

        __syncthreads();
        if (tid == 0) {
            __threadfence();
            const int old = atomicAdd(&g_sync2, 1);
            if (old == 31) {
                *(volatile int*)&g_sync1 = 0;
                *(volatile int*)&g_sync2 = 0;
                __threadfence();
            }
        }
    }
}

// ================= main: recurrence + CNT-GEMM + out-GEMM ===================
// grid 256 x 512; block = 128 batches; 2 blocks/SM (single wave).
// smem (floats):
//   A-region [0, 17544): phase A: sSk[64*68]u | sQP[66*68] | sCNT[128*68]
//                        phase B: sH[64*136] | sWhi[64*68] | sWlo[64*68]
//   fixed: sMP[64*72] | sRB[64] | sQT[128 int] | sTok[3072 B]
#define UA_F 17544
#define MAIN_SMEM_BYTES ((UA_F + 64*72 + 64 + 128) * 4 + 128 * 24)

__global__ void __launch_bounds__(512, 2) main_kernel(
    const int* __restrict__ seqs32, const int* __restrict__ qtok32,
    const float* __restrict__ rb2,  float* __restrict__ out)
{
    extern __shared__ float sm[];
    uint32_t* sSk = (uint32_t*)sm;         // [64][68]  (phase A)
    float* sQP  = sm + 4352;               // [66][68]  (phase A)
    float* sCNT = sm + 8840;               // [128][68] (phase A)
    float* sH   = sm;                      // [64][136] (phase B)
    float* sWhi = sm + 8704;               // [64][68]  (phase B)
    float* sWlo = sm + 13056;              // [64][68]  (phase B)
    float* sMP  = sm + UA_F;               // [64][72]
    float* sRB  = sMP + 64 * 72;           // [64]
    int*   sQT  = (int*)(sRB + 64);        // [128]
    unsigned char* sTok = (unsigned char*)(sQT + 128);
    const int tid = threadIdx.x, bid = blockIdx.x;
    const int w = tid >> 5, lane = tid & 31;
    const int g = lane >> 2, tg = lane & 3;

    const int oddS = seqs32[1] | seqs32[3] | seqs32[5] | seqs32[7] |
                     seqs32[9] | seqs32[11] | seqs32[13] | seqs32[15];
    const bool is64s = (oddS == 0);
    const int oddQ = qtok32[1] | qtok32[3] | qtok32[5] | qtok32[7] |
                     qtok32[9] | qtok32[11] | qtok32[13] | qtok32[15];
    const bool is64q = (oddQ == 0);

    // ---- phase 0: float4 staging of keys/QP, zero CNT, tokens ----
    for (int i = tid; i < 1088; i += 512)
        ((uint4*)sSk)[i] = ((const uint4*)g_Sk)[i];
    for (int i = tid; i < 1122; i += 512)
        ((float4*)sQP)[i] = ((const float4*)g_QP)[i];
    {
        const float4 z = {0.f, 0.f, 0.f, 0.f};
        for (int i = tid; i < 2176; i += 512) ((float4*)sCNT)[i] = z;
    }
    {
        const int base = bid * 128 * 24;
        for (int i = tid; i < 3072; i += 512) {
            const int v = is64s ? seqs32[2 * (base + i)] : seqs32[base + i];
            sTok[i] = (unsigned char)v;
        }
    }
    if (tid < 128) {
        const int b = bid * 128 + tid;
        sQT[tid] = is64q ? qtok32[2 * b] : qtok32[b];
    }
    __syncthreads();

    // ---- phase 1: warps 0-3 recurrence+scatter; warps 4-15 stage MP+bias ----
    if (w < 4) {
        const unsigned char* myTok = sTok + tid * 24;
        int mt[8];
        #pragma unroll
        for (int s = 0; s < 8; s++) mt[s] = myTok[s];
        #pragma unroll
        for (int t = 8; t < 23; t++) {
            const int c = myTok[t];
            const uint32_t* Srow = sSk + c * 68;
            unsigned key[8];
            #pragma unroll
            for (int s = 0; s < 8; s++)
                key[s] = Srow[mt[s]] | (unsigned)(3 - (s & 3));
            const unsigned a0 = max(max(key[0], key[1]), max(key[2], key[3]));
            const unsigned a1 = max(max(key[4], key[5]), max(key[6], key[7]));
            const int bi = ((a1 >> 2) > (a0 >> 2)) ? (4 + 3 - (int)(a1 & 3))
                                                   : (3 - (int)(a0 & 3));
            #pragma unroll
            for (int s = 0; s < 8; s++) if (bi == s) mt[s] = c;
        }
        float* cr = sCNT + tid * 68;
        #pragma unroll
        for (int s = 0; s < 8; s++) cr[mt[s]] += 0.125f;
    } else {
        const int t2 = tid - 128;
        for (int i = t2; i < 1024; i += 384) {
            const int r = i >> 4, c4 = i & 15;
            ((float4*)(sMP + r * 72))[c4] = ((const float4*)g_MP)[r * 17 + c4];
        }
        for (int i = t2; i < 16; i += 384)
            ((float4*)sRB)[i] = ((const float4*)rb2)[i];
    }
    __syncthreads();

    // ---- phase 2: GEMM1  C1 = CNT @ MP  (single mma: CNT exact, MP rounded)
    const int bm0 = (w & 7) * 16;
    const int jh  = (w >> 3) * 32;
    float c1[4][4];
    #pragma unroll
    for (int t = 0; t < 4; t++)
        { c1[t][0] = 0.f; c1[t][1] = 0.f; c1[t][2] = 0.f; c1[t][3] = 0.f; }

    #pragma unroll
    for (int k0 = 0; k0 < 64; k0 += 8) {
        const float* ap = sCNT + (bm0 + g) * 68 + k0 + tg;
        const uint32_t a0 = __float_as_uint(ap[0]);
        const uint32_t a1 = __float_as_uint(ap[8 * 68]);
        const uint32_t a2 = __float_as_uint(ap[4]);
        const uint32_t a3 = __float_as_uint(ap[8 * 68 + 4]);
        #pragma unroll
        for (int t = 0; t < 4; t++) {
            const int jn0 = jh + t * 8;
            const uint32_t b0 = __float_as_uint(sMP[(k0 + tg) * 72 + jn0 + g]);
            const uint32_t b1 = __float_as_uint(sMP[(k0 + tg + 4) * 72 + jn0 + g]);
            mma_tf32(c1[t], a0, a1, a2, a3, b0, b1);
        }
    }

    // ---- QP add + relu + tf32 round (single-precision H) ----
    float hh[16];
    {
        const int qt0 = sQT[bm0 + g], qt1 = sQT[bm0 + 8 + g];
        #pragma unroll
        for (int t = 0; t < 4; t++) {
            const int jj = jh + t * 8 + 2 * tg;
            const float2 q0 = *(const float2*)(sQP + qt0 * 68 + jj);
            const float2 q1 = *(const float2*)(sQP + qt1 * 68 + jj);
            hh[t*4+0] = tf32r(fmaxf(c1[t][0] + q0.x, 0.f));
            hh[t*4+1] = tf32r(fmaxf(c1[t][1] + q0.y, 0.f));
            hh[t*4+2] = tf32r(fmaxf(c1[t][2] + q1.x, 0.f));
            hh[t*4+3] = tf32r(fmaxf(c1[t][3] + q1.y, 0.f));
        }
    }
    __syncthreads();   // region-A phase-A reads complete

    // ---- phase 3: store H (j-major) + stage pre-split W ----
    #pragma unroll
    for (int t = 0; t < 4; t++) {
        const int jj = jh + t * 8 + 2 * tg;
        sH[jj * 136 + bm0 + g]           = hh[t*4+0];
        sH[(jj + 1) * 136 + bm0 + g]     = hh[t*4+1];
        sH[jj * 136 + bm0 + 8 + g]       = hh[t*4+2];
        sH[(jj + 1) * 136 + bm0 + 8 + g] = hh[t*4+3];
    }
    for (int i = tid; i < 1088; i += 512)
        ((float4*)sWhi)[i] = ((const float4*)g_Whi)[i];
    for (int i = tid; i < 1088; i += 512)
        ((float4*)sWlo)[i] = ((const float4*)g_Wlo)[i];
    __syncthreads();

    // ---- phase 4: GEMM2  out^T = W^T @ H  (2 mma: Whi + Wlo, H exact-tf32)
    const int v0 = (w & 3) * 16;
    const int bb = (w >> 2) * 32;
    float acc[4][4];
    {
        const float bias0 = sRB[v0 + g], bias1 = sRB[v0 + g + 8];
        #pragma unroll
        for (int t = 0; t < 4; t++) {
            acc[t][0] = bias0; acc[t][1] = bias0;
            acc[t][2] = bias1; acc[t][3] = bias1;
        }
    }
    #pragma unroll
    for (int k0 = 0; k0 < 64; k0 += 8) {
        const float* wh = sWhi + (v0 + g) * 68 + k0 + tg;
        const float* wl = sWlo + (v0 + g) * 68 + k0 + tg;
        const uint32_t ah0 = __float_as_uint(wh[0]);
        const uint32_t ah1 = __float_as_uint(wh[8 * 68]);
        const uint32_t ah2 = __float_as_uint(wh[4]);
        const uint32_t ah3 = __float_as_uint(wh[8 * 68 + 4]);
        const uint32_t al0 = __float_as_uint(wl[0]);
        const uint32_t al1 = __float_as_uint(wl[8 * 68]);
        const uint32_t al2 = __float_as_uint(wl[4]);
        const uint32_t al3 = __float_as_uint(wl[8 * 68 + 4]);
        #pragma unroll
        for (int t = 0; t < 4; t++) {
            const int bcol = bb + t * 8 + g;
            const uint32_t bh0 = __float_as_uint(sH[(k0 + tg) * 136 + bcol]);
            const uint32_t bh1 = __float_as_uint(sH[(k0 + tg + 4) * 136 + bcol]);
            mma_tf32(acc[t], ah0, ah1, ah2, ah3, bh0, bh1);
            mma_tf32(acc[t], al0, al1, al2, al3, bh0, bh1);
        }
    }
    #pragma unroll
    for (int t = 0; t < 4; t++) {
        const int b = bid * 128 + bb + t * 8 + tg * 2;
        const int v = v0 + g;
        out[b * 64 + v]           = acc[t][0];
        out[(b + 1) * 64 + v]     = acc[t][1];
        out[b * 64 + v + 8]       = acc[t][2];
        out[(b + 1) * 64 + v + 8] = acc[t][3];
    }
}

// ============================== launch ======================================
extern "C" void kernel_launch(void* const* d_in, const int* in_sizes, int n_in,
                              void* d_out, int out_size)
{
    const int*   seqs  = (const int*)  d_in[0];
    const int*   qtok  = (const int*)  d_in[1];
    const float* embed = (const float*)d_in[2];
    const float* gw1   = (const float*)d_in[3];
    const float* gb1   = (const float*)d_in[4];
    const float* gw2   = (const float*)d_in[5];
    const float* gb2   = (const float*)d_in[6];
    const float* rw1   = (const float*)d_in[7];
    const float* rb1   = (const float*)d_in[8];
    const float* rw2   = (const float*)d_in[9];
    const float* rb2   = (const float*)d_in[10];

    cudaFuncSetAttribute(main_kernel,
                         cudaFuncAttributeMaxDynamicSharedMemorySize,
                         MAIN_SMEM_BYTES);

    pre_kernel<<<129, 512>>>(embed, gw1, rw1, rb1, gb1, gw2, gb2, rw2);
    main_kernel<<<256, 512, MAIN_SMEM_BYTES>>>(seqs, qtok, rb2, (float*)d_out);
}

// round 17
// speedup vs baseline: 1.5385x; 1.0986x over previous
#include <cuda_runtime.h>
#include <math.h>
#include <stdint.h>

// ---------------------------------------------------------------------------
// SelectiveModel: B=32768, T=23, H=64, SLOTS=8, VOCAB=64.
//
// R17: ONE kernel. Grid 256 x 512, 2 blocks/SM (capacity 296 >= 256 -> all
// co-resident; grid-wide spin barriers are safe, self-resetting for graph
// replay).
//   blocks 0-96  : 12416 dot-64s (4 thr/dot)          -> g_ED/MDT/QP/MP
//   blocks 129-136: W^T tf32 round                     -> g_Whi
//   barrier1 (105 producers)
//   blocks 97-128: S-key table                         -> g_Sk
//   all: stage QP/CNT/MP/Whi/tok -> barrier2 (32) -> stage Sk
//   then per-block: recurrence -> CNT@MP (1 mma) -> +QP,relu -> W^T@H (1 mma)
// GEMM2 now single-mma (W tf32): rel_err ~3e-4 expected (tol 1e-3).
// ---------------------------------------------------------------------------

#define BTOT 32768

__device__ uint32_t g_Sk [64 * 68];   // sigmoid-score keys, bits<<2, padded
__device__ float    g_QP [66 * 68];
__device__ float    g_MP [64 * 68];   // tf32-rounded
__device__ float    g_Whi[64 * 68];   // W^T tf32-rounded, [v][k]
__device__ float    g_ED [64 * 32];
__device__ float    g_MDT[32 * 64];
__device__ int      g_sync1 = 0;      // dots + W producers (105)
__device__ int      g_sync2 = 0;      // S producers (32)
__device__ int      g_sync3 = 0;      // end-of-kernel arrivals (256) -> reset

__device__ __forceinline__ float tf32r(float x) {
    uint32_t r;
    asm("cvt.rna.tf32.f32 %0, %1;" : "=r"(r) : "f"(x));
    return __uint_as_float(r);
}
__device__ __forceinline__ void mma_tf32(float* c,
    uint32_t a0, uint32_t a1, uint32_t a2, uint32_t a3,
    uint32_t b0, uint32_t b1)
{
    asm volatile(
        "mma.sync.aligned.m16n8k8.row.col.f32.tf32.tf32.f32 "
        "{%0,%1,%2,%3},{%4,%5,%6,%7},{%8,%9},{%0,%1,%2,%3};"
        : "+f"(c[0]), "+f"(c[1]), "+f"(c[2]), "+f"(c[3])
        : "r"(a0), "r"(a1), "r"(a2), "r"(a3), "r"(b0), "r"(b1));
}

// smem layout (floats):
//   sSk  @0      4352 (u32)   | sQP @4352   4488 | U @8840 8704
//   sWhi @17544  4352         | sMP @21896  4608 | sRB @26504 64
//   sQT  @26568  128 (int)    | sTok @26696 768  -> total 27464 f = 109856 B
#define MAIN_SMEM_BYTES (27464 * 4)

__global__ void __launch_bounds__(512, 2) fused_kernel(
    const int* __restrict__ seqs32, const int* __restrict__ qtok32,
    const float* __restrict__ embed, const float* __restrict__ gw1,
    const float* __restrict__ gb1,   const float* __restrict__ gw2,
    const float* __restrict__ gb2,   const float* __restrict__ rw1,
    const float* __restrict__ rb1,   const float* __restrict__ rw2,
    const float* __restrict__ rb2,   float* __restrict__ out)
{
    extern __shared__ float sm[];
    uint32_t* sSk = (uint32_t*)sm;         // [64][68]
    float* sQP  = sm + 4352;               // [66][68]
    float* sCNT = sm + 8840;               // [128][68] (phase A of U)
    float* sH   = sm + 8840;               // [64][136] (phase B of U)
    float* sWhi = sm + 17544;              // [64][68]
    float* sMP  = sm + 21896;              // [64][72]
    float* sRB  = sm + 26504;              // [64]
    int*   sQT  = (int*)(sm + 26568);      // [128]
    unsigned char* sTok = (unsigned char*)(sm + 26696);
    const int tid = threadIdx.x, bid = blockIdx.x;
    const int w = tid >> 5, lane = tid & 31;
    const int g = lane >> 2, tg = lane & 3;

    // ==================== pre-slice (table construction) ====================
    if (bid < 97) {
        // ---- dots: 4 threads per dot, k-split 16, shfl reduce ----
        const int gid = bid * 512 + tid;
        const int d = gid >> 2, tg4 = gid & 3;
        const int k0 = tg4 * 16;
        if (d < 4096) {
            const int r = d >> 5, j = d & 31;
            const float* e = embed + (r & 63) * 64 + k0;
            const float* ww = gw1 + ((r >> 6) * 64 + k0) * 32 + j;
            float er[16], wr[16];
            #pragma unroll
            for (int i = 0; i < 16; i++) { er[i] = e[i]; wr[i] = ww[i * 32]; }
            float a[4] = {0.f, 0.f, 0.f, 0.f};
            #pragma unroll
            for (int i = 0; i < 16; i++) a[i & 3] += er[i] * wr[i];
            float p = (a[0] + a[1]) + (a[2] + a[3]);
            p += __shfl_xor_sync(0xffffffff, p, 1, 4);
            p += __shfl_xor_sync(0xffffffff, p, 2, 4);
            if (tg4 == 0) {
                if (r < 64) g_ED[r * 32 + j] = p;
                else        g_MDT[j * 64 + (r - 64)] = p;
            }
        } else {
            const bool isQP = (d < 8320);
            const int e2 = isQP ? (d - 4096) : (d - 8320);
            const int r = e2 >> 6, j = e2 & 63;
            const float* e = embed + r * 64 + k0;
            const float* ww = rw1 + (isQP ? 0 : 64 * 64) + k0 * 64 + j;
            float er[16], wr[16];
            #pragma unroll
            for (int i = 0; i < 16; i++) { er[i] = e[i]; wr[i] = ww[i * 64]; }
            float a[4] = {0.f, 0.f, 0.f, 0.f};
            #pragma unroll
            for (int i = 0; i < 16; i++) a[i & 3] += er[i] * wr[i];
            float p = (a[0] + a[1]) + (a[2] + a[3]);
            p += __shfl_xor_sync(0xffffffff, p, 1, 4);
            p += __shfl_xor_sync(0xffffffff, p, 2, 4);
            if (tg4 == 0) {
                if (isQP) {
                    g_QP[r * 68 + j] = p + rb1[j];
                    if (j < 4) g_QP[r * 68 + 64 + j] = 0.f;
                } else {
                    g_MP[r * 68 + j] = tf32r(p);
                    if (j < 4) g_MP[r * 68 + 64 + j] = 0.f;
                }
            }
        }
        __syncthreads();
        if (tid == 0) { __threadfence(); atomicAdd(&g_sync1, 1); }
    } else if (bid >= 129 && bid < 137) {
        // ---- W^T tf32 round ----
        const int gid = (bid - 129) * 512 + tid;   // [0, 4096)
        const int k = gid >> 6, v = gid & 63;
        g_Whi[v * 68 + k] = tf32r(rw2[gid]);
        __syncthreads();
        if (tid == 0) { __threadfence(); atomicAdd(&g_sync1, 1); }
    }

    // ---- barrier 1: dots + W done ----
    if (tid == 0) {
        while (*(volatile int*)&g_sync1 < 105) { }
        __threadfence();
    }
    __syncthreads();

    // ---- S-key blocks ----
    if (bid >= 97 && bid < 129) {
        const int gid = (bid - 97) * 512 + tid;    // [0, 16384)
        const int idx = gid >> 2, tg4 = gid & 3;
        const int c = idx >> 6, m = idx & 63;
        const int j0 = tg4 * 8;
        const float* ed = g_ED + c * 32 + j0;
        float md[8], edv[8], gb[8], gw[8];
        #pragma unroll
        for (int i = 0; i < 8; i++) {
            md[i]  = g_MDT[(j0 + i) * 64 + m];
            edv[i] = ed[i];
            gb[i]  = gb1[j0 + i];
            gw[i]  = gw2[j0 + i];
        }
        float p = 0.f;
        #pragma unroll
        for (int i = 0; i < 8; i++)
            p += fmaxf(edv[i] + md[i] + gb[i], 0.f) * gw[i];
        p += __shfl_xor_sync(0xffffffff, p, 1, 4);
        p += __shfl_xor_sync(0xffffffff, p, 2, 4);
        if (tg4 == 0) {
            const float s = 1.f / (1.f + expf(-(p + gb2[0])));
            g_Sk[c * 68 + m] = __float_as_uint(s) << 2;
        }
        __syncthreads();
        if (tid == 0) { __threadfence(); atomicAdd(&g_sync2, 1); }
    }

    // ==================== per-block staging ====================
    const int oddS = seqs32[1] | seqs32[3] | seqs32[5] | seqs32[7] |
                     seqs32[9] | seqs32[11] | seqs32[13] | seqs32[15];
    const bool is64s = (oddS == 0);
    const int oddQ = qtok32[1] | qtok32[3] | qtok32[5] | qtok32[7] |
                     qtok32[9] | qtok32[11] | qtok32[13] | qtok32[15];
    const bool is64q = (oddQ == 0);

    for (int i = tid; i < 1122; i += 512)
        ((float4*)sQP)[i] = ((const float4*)g_QP)[i];
    {
        const float4 z = {0.f, 0.f, 0.f, 0.f};
        for (int i = tid; i < 2176; i += 512) ((float4*)sCNT)[i] = z;
    }
    for (int i = tid; i < 1024; i += 512) {
        const int r = i >> 4, c4 = i & 15;
        ((float4*)(sMP + r * 72))[c4] = ((const float4*)g_MP)[r * 17 + c4];
    }
    for (int i = tid; i < 1088; i += 512)
        ((float4*)sWhi)[i] = ((const float4*)g_Whi)[i];
    if (tid < 16) ((float4*)sRB)[tid] = ((const float4*)rb2)[tid];
    {
        const int base = bid * 128 * 24;
        for (int i = tid; i < 3072; i += 512) {
            const int v = is64s ? seqs32[2 * (base + i)] : seqs32[base + i];
            sTok[i] = (unsigned char)v;
        }
    }
    if (tid < 128) {
        const int b = bid * 128 + tid;
        sQT[tid] = is64q ? qtok32[2 * b] : qtok32[b];
    }

    // ---- barrier 2: S-keys ready ----
    if (tid == 0) {
        while (*(volatile int*)&g_sync2 < 32) { }
        __threadfence();
    }
    __syncthreads();
    for (int i = tid; i < 1088; i += 512)
        ((uint4*)sSk)[i] = ((const uint4*)g_Sk)[i];
    __syncthreads();

    // ==================== phase 1: recurrence + CNT scatter ==================
    if (w < 4) {
        const unsigned char* myTok = sTok + tid * 24;
        int mt[8];
        #pragma unroll
        for (int s = 0; s < 8; s++) mt[s] = myTok[s];
        #pragma unroll
        for (int t = 8; t < 23; t++) {
            const int c = myTok[t];
            const uint32_t* Srow = sSk + c * 68;
            unsigned key[8];
            #pragma unroll
            for (int s = 0; s < 8; s++)
                key[s] = Srow[mt[s]] | (unsigned)(3 - (s & 3));
            const unsigned a0 = max(max(key[0], key[1]), max(key[2], key[3]));
            const unsigned a1 = max(max(key[4], key[5]), max(key[6], key[7]));
            const int bi = ((a1 >> 2) > (a0 >> 2)) ? (4 + 3 - (int)(a1 & 3))
                                                   : (3 - (int)(a0 & 3));
            #pragma unroll
            for (int s = 0; s < 8; s++) if (bi == s) mt[s] = c;
        }
        float* cr = sCNT + tid * 68;
        #pragma unroll
        for (int s = 0; s < 8; s++) cr[mt[s]] += 0.125f;
    }
    __syncthreads();

    // ==================== phase 2: GEMM1  C1 = CNT @ MP (1 mma) ==============
    const int bm0 = (w & 7) * 16;
    const int jh  = (w >> 3) * 32;
    float c1[4][4];
    #pragma unroll
    for (int t = 0; t < 4; t++)
        { c1[t][0] = 0.f; c1[t][1] = 0.f; c1[t][2] = 0.f; c1[t][3] = 0.f; }

    #pragma unroll
    for (int k0 = 0; k0 < 64; k0 += 8) {
        const float* ap = sCNT + (bm0 + g) * 68 + k0 + tg;
        const uint32_t a0 = __float_as_uint(ap[0]);
        const uint32_t a1 = __float_as_uint(ap[8 * 68]);
        const uint32_t a2 = __float_as_uint(ap[4]);
        const uint32_t a3 = __float_as_uint(ap[8 * 68 + 4]);
        #pragma unroll
        for (int t = 0; t < 4; t++) {
            const int jn0 = jh + t * 8;
            const uint32_t b0 = __float_as_uint(sMP[(k0 + tg) * 72 + jn0 + g]);
            const uint32_t b1 = __float_as_uint(sMP[(k0 + tg + 4) * 72 + jn0 + g]);
            mma_tf32(c1[t], a0, a1, a2, a3, b0, b1);
        }
    }

    // ---- QP add + relu + tf32 round ----
    float hh[16];
    {
        const int qt0 = sQT[bm0 + g], qt1 = sQT[bm0 + 8 + g];
        #pragma unroll
        for (int t = 0; t < 4; t++) {
            const int jj = jh + t * 8 + 2 * tg;
            const float2 q0 = *(const float2*)(sQP + qt0 * 68 + jj);
            const float2 q1 = *(const float2*)(sQP + qt1 * 68 + jj);
            hh[t*4+0] = tf32r(fmaxf(c1[t][0] + q0.x, 0.f));
            hh[t*4+1] = tf32r(fmaxf(c1[t][1] + q0.y, 0.f));
            hh[t*4+2] = tf32r(fmaxf(c1[t][2] + q1.x, 0.f));
            hh[t*4+3] = tf32r(fmaxf(c1[t][3] + q1.y, 0.f));
        }
    }
    __syncthreads();   // all CNT reads complete before U reuse

    // ==================== phase 3: store H (j-major) =========================
    #pragma unroll
    for (int t = 0; t < 4; t++) {
        const int jj = jh + t * 8 + 2 * tg;
        sH[jj * 136 + bm0 + g]           = hh[t*4+0];
        sH[(jj + 1) * 136 + bm0 + g]     = hh[t*4+1];
        sH[jj * 136 + bm0 + 8 + g]       = hh[t*4+2];
        sH[(jj + 1) * 136 + bm0 + 8 + g] = hh[t*4+3];
    }
    __syncthreads();

    // ==================== phase 4: GEMM2  out^T = W^T @ H (1 mma) ============
    const int v0 = (w & 3) * 16;
    const int bb = (w >> 2) * 32;
    float acc[4][4];
    {
        const float bias0 = sRB[v0 + g], bias1 = sRB[v0 + g + 8];
        #pragma unroll
        for (int t = 0; t < 4; t++) {
            acc[t][0] = bias0; acc[t][1] = bias0;
            acc[t][2] = bias1; acc[t][3] = bias1;
        }
    }
    #pragma unroll
    for (int k0 = 0; k0 < 64; k0 += 8) {
        const float* wh = sWhi + (v0 + g) * 68 + k0 + tg;
        const uint32_t ah0 = __float_as_uint(wh[0]);
        const uint32_t ah1 = __float_as_uint(wh[8 * 68]);
        const uint32_t ah2 = __float_as_uint(wh[4]);
        const uint32_t ah3 = __float_as_uint(wh[8 * 68 + 4]);
        #pragma unroll
        for (int t = 0; t < 4; t++) {
            const int bcol = bb + t * 8 + g;
            const uint32_t bh0 = __float_as_uint(sH[(k0 + tg) * 136 + bcol]);
            const uint32_t bh1 = __float_as_uint(sH[(k0 + tg + 4) * 136 + bcol]);
            mma_tf32(acc[t], ah0, ah1, ah2, ah3, bh0, bh1);
        }
    }
    #pragma unroll
    for (int t = 0; t < 4; t++) {
        const int b = bid * 128 + bb + t * 8 + tg * 2;
        const int v = v0 + g;
        out[b * 64 + v]           = acc[t][0];
        out[(b + 1) * 64 + v]     = acc[t][1];
        out[b * 64 + v + 8]       = acc[t][2];
        out[(b + 1) * 64 + v + 8] = acc[t][3];
    }

    // ---- end arrival: last block resets counters (graph-replay safe) ----
    if (tid == 0) {
        const int old = atomicAdd(&g_sync3, 1);
        if (old == 255) {
            *(volatile int*)&g_sync1 = 0;
            *(volatile int*)&g_sync2 = 0;
            *(volatile int*)&g_sync3 = 0;
            __threadfence();
        }
    }
}

// ============================== launch ======================================
extern "C" void kernel_launch(void* const* d_in, const int* in_sizes, int n_in,
                              void* d_out, int out_size)
{
    const int*   seqs  = (const int*)  d_in[0];
    const int*   qtok  = (const int*)  d_in[1];
    const float* embed = (const float*)d_in[2];
    const float* gw1   = (const float*)d_in[3];
    const float* gb1   = (const float*)d_in[4];
    const float* gw2   = (const float*)d_in[5];
    const float* gb2   = (const float*)d_in[6];
    const float* rw1   = (const float*)d_in[7];
    const float* rb1   = (const float*)d_in[8];
    const float* rw2   = (const float*)d_in[9];
    const float* rb2   = (const float*)d_in[10];

    cudaFuncSetAttribute(fused_kernel,
                         cudaFuncAttributeMaxDynamicSharedMemorySize,
                         MAIN_SMEM_BYTES);

    fused_kernel<<<256, 512, MAIN_SMEM_BYTES>>>(
        seqs, qtok, embed, gw1, gb1, gw2, gb2, rw1, rb1, rw2, rb2,
        (float*)d_out);
}